// round 17
// baseline (speedup 1.0000x reference)
#include <cuda_runtime.h>

// Problem shapes (fixed per reference setup_inputs)
#define BB  2
#define SS  2048
#define HH  4096
#define NHD 32
#define NSL 100
#define NP  128          // slots padded to 128
#define DD  64
#define BSR (BB*SS)      // 4096 rows

typedef unsigned long long ull;

// -------- scratch (no allocations allowed) --------
__device__ float g_gate[BSR];
__device__ float g_KW[HH*NP];        // (W_q^T keys^T)[h][n]
__device__ float g_logrelp[NP];      // log(rel+eps), pad = -1e30
__device__ float g_attn[BSR*NP];     // softmax(scores), un-gated
__device__ unsigned g_row_ticket;
__device__ unsigned g_out_ticket;
__device__ unsigned g_tile_ready[BSR/32];  // per row-tile: 32 (gates) + 32 (attn)

// -------- packed f32x2 helpers --------
__device__ __forceinline__ ull pk2(float lo, float hi){
    ull r; asm("mov.b64 %0, {%1, %2};" : "=l"(r) : "f"(lo), "f"(hi)); return r;
}
__device__ __forceinline__ void upk2(ull v, float& lo, float& hi){
    asm("mov.b64 {%0, %1}, %2;" : "=f"(lo), "=f"(hi) : "l"(v));
}
__device__ __forceinline__ void fma2(ull& d, ull a, ull b){
    asm("fma.rn.f32x2 %0, %1, %2, %0;" : "+l"(d) : "l"(a), "l"(b));
}
union F4U { float4 f; ull u[2]; };

// ============================================================
// prep_kw: KW, logrel, and ALL tickets/flags reset
// grid (16, 8) x 256
// ============================================================
__global__ __launch_bounds__(256)
void prep_kw(const float* __restrict__ Wq,
             const float* __restrict__ keys,
             const float* __restrict__ rel)
{
    __shared__ float sk[16*DD];
    int t = threadIdx.x;
    int n0 = blockIdx.y * 16;
    for (int i = t; i < 16*DD; i += 256) {
        int n = i >> 6, d = i & 63;
        sk[i] = ((n0 + n) < NSL) ? keys[(n0+n)*DD + d] : 0.f;
    }
    __syncthreads();

    int h = blockIdx.x*256 + t;
    float wv[DD];
    #pragma unroll
    for (int d = 0; d < DD; ++d) wv[d] = Wq[(size_t)d*HH + h];

    #pragma unroll 4
    for (int n = 0; n < 16; ++n) {
        float acc = 0.f;
        const float* kn = sk + n*DD;
        #pragma unroll
        for (int d = 0; d < DD; ++d) acc += wv[d]*kn[d];
        g_KW[(size_t)h*NP + n0 + n] = acc;
    }
    if (blockIdx.x == 0 && blockIdx.y == 0) {
        if (t < NP) g_logrelp[t] = (t < NSL) ? __logf(rel[t] + 1e-10f) : -1e30f;
        if (t < BSR/32) g_tile_ready[t] = 0u;
        if (t == 0) { g_row_ticket = 0u; g_out_ticket = 0u; }
    }
}

// ============================================================
// merged mega: grid 296 (2 CTAs/SM), 256 thr.
//   blocks [0,148) & [276,296): worker loop (entropy-priority)
//   blocks [148,276): one scores tile -> publish attn -> worker
// Worker loop: dependency-aware stealing between entropy rows
// and output tiles (32 rows x 256 cols, 2048 tiles).
// ============================================================
#define NENT  148
#define NSCORE 128
#define NGRID (NENT + NSCORE + 20)   // 296

#define SKC 64
#define NCH (HH/SKC)     // 64 chunks
#define SCORES_SMEM (32*SKC*2 + SKC*NP)   // 49152B

#define NOTILE (BSR/32 * 16)   // 2048 output tiles (256 cols each)
#define TNONE 0xffffffffu

// ---- one entropy row (publishes gate + readiness) ----
__device__ __forceinline__ void entropy_row(const float* __restrict__ paw,
                                            float w1, float bb,
                                            unsigned row, float* red)
{
    int t = threadIdx.x;
    size_t b = (size_t)(row >> 11);
    size_t s = (size_t)(row & 2047);
    const float* base = paw + ((b*NHD)*SS + s) * (size_t)SS;

    float4 a0 = make_float4(0.f,0.f,0.f,0.f);
    float4 a1 = make_float4(0.f,0.f,0.f,0.f);
    for (int h0 = 0; h0 < NHD; h0 += 8) {
        float4 x0[8], x1[8];
        #pragma unroll
        for (int u = 0; u < 8; ++u) {
            const float4* p = (const float4*)(base + (size_t)(h0+u)*SS*SS);
            x0[u] = p[t];
            x1[u] = p[t + 256];
        }
        #pragma unroll
        for (int u = 0; u < 8; ++u) {
            a0.x += x0[u].x; a0.y += x0[u].y; a0.z += x0[u].z; a0.w += x0[u].w;
            a1.x += x1[u].x; a1.y += x1[u].y; a1.z += x1[u].z; a1.w += x1[u].w;
        }
    }
    const float inv = 1.0f / 32.0f;
    float v[8] = {a0.x,a0.y,a0.z,a0.w,a1.x,a1.y,a1.z,a1.w};
    float loc = 0.f;
    #pragma unroll
    for (int i = 0; i < 8; ++i) {
        float a = v[i] * inv;
        loc += a * __logf(a + 1e-10f);
    }
    #pragma unroll
    for (int o = 16; o; o >>= 1) loc += __shfl_xor_sync(0xffffffffu, loc, o);
    if ((t & 31) == 0) red[t >> 5] = loc;
    __syncthreads();
    if (t == 0) {
        float tot = 0.f;
        #pragma unroll
        for (int i = 0; i < 8; ++i) tot += red[i];
        float e = -tot;
        float g = 1.0f / (1.0f + __expf(-(w1*e + bb)));
        if (e < 0.5f)       g = 0.f;
        else if (e > 2.0f)  g = fminf(g, 0.8f);
        g_gate[row] = g;
        __threadfence();
        atomicAdd(&g_tile_ready[row >> 5], 1u);
    }
}

// ---- one output tile: 32 rows x 256 cols ----
__device__ __forceinline__ void output_tile(const float* __restrict__ primary,
                                            const float* __restrict__ vals,
                                            float* __restrict__ out,
                                            unsigned tile, ull* attn2, float* sg)
{
    int t = threadIdx.x;
    int row0 = (int)(tile >> 4) * 32;
    int c    = (int)(tile & 15) * 256 + t;

    if (t < 32) sg[t] = g_gate[row0 + t];
    __syncthreads();
    for (int idx = t; idx < NSL*16; idx += 256) {
        int n = idx >> 4, rp = idx & 15;
        float a0 = g_attn[(size_t)(row0 + 2*rp  )*NP + n];
        float a1 = g_attn[(size_t)(row0 + 2*rp+1)*NP + n];
        attn2[n*16 + rp] = pk2(a0*sg[2*rp], a1*sg[2*rp+1]);
    }
    __syncthreads();

    ull acc[16];
    #pragma unroll
    for (int rp = 0; rp < 16; ++rp) {
        size_t rb = (size_t)(row0 + rp*2) * HH;
        acc[rp] = pk2(primary[rb + c], primary[rb + HH + c]);
    }

    float vr[8];
    #pragma unroll
    for (int i = 0; i < 8; ++i) vr[i] = vals[(size_t)i*HH + c];

    for (int n = 0; n < 96; n += 8) {
        #pragma unroll
        for (int u = 0; u < 8; ++u) {
            int nn = n + u;
            int np = (nn + 8 < NSL) ? nn + 8 : NSL-1;
            float nv = vals[(size_t)np*HH + c];
            ull vv = pk2(vr[u], vr[u]);
            const float4* arow = (const float4*)(attn2 + nn*16);
            #pragma unroll
            for (int j = 0; j < 8; ++j) {
                F4U x; x.f = arow[j];
                fma2(acc[2*j],   x.u[0], vv);
                fma2(acc[2*j+1], x.u[1], vv);
            }
            vr[u] = nv;
        }
    }
    #pragma unroll
    for (int u = 0; u < 4; ++u) {
        int nn = 96 + u;
        ull vv = pk2(vr[u], vr[u]);
        const float4* arow = (const float4*)(attn2 + nn*16);
        #pragma unroll
        for (int j = 0; j < 8; ++j) {
            F4U x; x.f = arow[j];
            fma2(acc[2*j],   x.u[0], vv);
            fma2(acc[2*j+1], x.u[1], vv);
        }
    }

    #pragma unroll
    for (int rp = 0; rp < 16; ++rp) {
        float x, y;
        size_t rb = (size_t)(row0 + rp*2) * HH;
        upk2(acc[rp], x, y);
        out[rb + c] = x;
        out[rb + HH + c] = y;
    }
}

__global__ __launch_bounds__(256, 2)
void mega_kernel(const float* __restrict__ hidden,
                 const float* __restrict__ paw,
                 const float* __restrict__ primary,
                 const float* __restrict__ vals,
                 const float* __restrict__ w1p,
                 const float* __restrict__ bp,
                 float* __restrict__ out)
{
    extern __shared__ float smraw[];
    __shared__ float red[8];
    __shared__ float sg[32];
    __shared__ int s_mode;
    __shared__ unsigned s_arg;
    __shared__ unsigned s_held;
    int t = threadIdx.x;
    int bid = blockIdx.x;
    const float w1 = w1p[0], bb = bp[0];

    if (bid >= NENT && bid < NENT + NSCORE) {
        // =================== one scores tile ===================
        float2* sh = (float2*)smraw;             // [32][SKC] dup pairs, 16KB
        float*  sw = smraw + 32*SKC*2;           // [SKC][NP], 32KB
        int w = t>>5, lane = t&31;
        int row0 = (bid - NENT)*32;

        float4 ph[2], pw[8];
        #pragma unroll
        for (int i = 0; i < 2; ++i) {
            int idx = t + i*256, rr = idx>>4, c4 = idx&15;
            ph[i] = *(const float4*)(hidden + (size_t)(row0+rr)*HH + (c4<<2));
        }
        #pragma unroll
        for (int i = 0; i < 8; ++i) {
            int idx = t + i*256, kk = idx>>5, c4 = idx&31;
            pw[i] = *(const float4*)(g_KW + (size_t)kk*NP + (c4<<2));
        }

        ull a[4][2] = {{0,0},{0,0},{0,0},{0,0}};

        for (int c = 0; c < NCH; ++c) {
            __syncthreads();
            #pragma unroll
            for (int i = 0; i < 2; ++i) {
                int idx = t + i*256, rr = idx>>4, c4 = idx&15;
                float2* d = &sh[rr*SKC + (c4<<2)];
                d[0] = make_float2(ph[i].x, ph[i].x);
                d[1] = make_float2(ph[i].y, ph[i].y);
                d[2] = make_float2(ph[i].z, ph[i].z);
                d[3] = make_float2(ph[i].w, ph[i].w);
            }
            #pragma unroll
            for (int i = 0; i < 8; ++i) {
                int idx = t + i*256, kk = idx>>5, c4 = idx&31;
                *(float4*)(sw + kk*NP + (c4<<2)) = pw[i];
            }
            __syncthreads();

            if (c + 1 < NCH) {
                int k0 = (c+1)*SKC;
                #pragma unroll
                for (int i = 0; i < 2; ++i) {
                    int idx = t + i*256, rr = idx>>4, c4 = idx&15;
                    ph[i] = *(const float4*)(hidden + (size_t)(row0+rr)*HH + k0 + (c4<<2));
                }
                #pragma unroll
                for (int i = 0; i < 8; ++i) {
                    int idx = t + i*256, kk = idx>>5, c4 = idx&31;
                    pw[i] = *(const float4*)(g_KW + (size_t)(k0+kk)*NP + (c4<<2));
                }
            }

            const ull* h0 = (const ull*)&sh[(w*4+0)*SKC];
            const ull* h1 = (const ull*)&sh[(w*4+1)*SKC];
            const ull* h2 = (const ull*)&sh[(w*4+2)*SKC];
            const ull* h3 = (const ull*)&sh[(w*4+3)*SKC];
            #pragma unroll 8
            for (int k = 0; k < SKC; ++k) {
                F4U kw; kw.f = *(const float4*)(sw + k*NP + (lane<<2));
                ull hh0 = h0[k], hh1 = h1[k], hh2 = h2[k], hh3 = h3[k];
                fma2(a[0][0], kw.u[0], hh0); fma2(a[0][1], kw.u[1], hh0);
                fma2(a[1][0], kw.u[0], hh1); fma2(a[1][1], kw.u[1], hh1);
                fma2(a[2][0], kw.u[0], hh2); fma2(a[2][1], kw.u[1], hh2);
                fma2(a[3][0], kw.u[0], hh3); fma2(a[3][1], kw.u[1], hh3);
            }
        }

        // softmax per row -> g_attn
        float4 lr = *(const float4*)(g_logrelp + (lane<<2));
        #pragma unroll
        for (int j = 0; j < 4; ++j) {
            int row = row0 + w*4 + j;
            float s0,s1,s2,s3;
            upk2(a[j][0], s0, s1); upk2(a[j][1], s2, s3);
            s0 = 0.125f*s0 + lr.x; s1 = 0.125f*s1 + lr.y;
            s2 = 0.125f*s2 + lr.z; s3 = 0.125f*s3 + lr.w;
            float m = fmaxf(fmaxf(s0,s1), fmaxf(s2,s3));
            #pragma unroll
            for (int o = 16; o; o >>= 1) m = fmaxf(m, __shfl_xor_sync(0xffffffffu, m, o));
            float e0 = __expf(s0-m), e1 = __expf(s1-m);
            float e2 = __expf(s2-m), e3 = __expf(s3-m);
            float sum = e0+e1+e2+e3;
            #pragma unroll
            for (int o = 16; o; o >>= 1) sum += __shfl_xor_sync(0xffffffffu, sum, o);
            float invs = 1.0f / sum;
            float4 o4 = make_float4(e0*invs, e1*invs, e2*invs, e3*invs);
            *(float4*)(g_attn + (size_t)row*NP + (lane<<2)) = o4;
        }
        // publish attn readiness (+32) for this row-tile
        __threadfence();
        __syncthreads();
        if (t == 0) atomicAdd(&g_tile_ready[row0 >> 5], 32u);
    }

    // =================== worker loop (all CTAs) ===================
    if (t == 0) s_held = TNONE;

    for (;;) {
        __syncthreads();          // protects s_* and smem reuse
        if (t == 0) {
            int mode = -1; unsigned arg = 0;
            unsigned held = s_held;
            // 1) held tile ready?
            if (held != TNONE &&
                ((volatile unsigned*)g_tile_ready)[held >> 4] >= 64u) {
                mode = 1; arg = held; s_held = TNONE;
            }
            // 2) entropy row available?
            if (mode < 0) {
                unsigned rk = atomicAdd(&g_row_ticket, 1u);
                if (rk < BSR) { mode = 0; arg = rk; }
            }
            // 3) no rows left: spin on held tile
            if (mode < 0 && held != TNONE) {
                while (((volatile unsigned*)g_tile_ready)[held >> 4] < 64u) ;
                mode = 1; arg = held; s_held = TNONE;
            }
            // 4) claim a new tile (retry loop)
            if (mode < 0) {
                unsigned tk = atomicAdd(&g_out_ticket, 1u);
                if (tk < NOTILE) { s_held = tk; mode = 2; }
            }
            s_mode = mode; s_arg = arg;
        }
        __syncthreads();
        int mode = s_mode;
        if (mode < 0) break;
        if (mode == 2) continue;
        if (mode == 0) {
            entropy_row(paw, w1, bb, s_arg, red);
        } else {
            __threadfence();      // acquire-ish before reading gates/attn
            output_tile(primary, vals, out, s_arg, (ull*)smraw, sg);
        }
    }
}

// ============================================================
extern "C" void kernel_launch(void* const* d_in, const int* in_sizes, int n_in,
                              void* d_out, int out_size)
{
    const float* hidden  = (const float*)d_in[0];  // [B,S,H]
    const float* primary = (const float*)d_in[1];  // [B,S,H]
    const float* paw     = (const float*)d_in[2];  // [B,NH,S,S]
    const float* rel     = (const float*)d_in[3];  // [NS]
    const float* Wq      = (const float*)d_in[4];  // [D,H]
    const float* keys    = (const float*)d_in[5];  // [NS,D]
    const float* vals    = (const float*)d_in[6];  // [NS,H]
    const float* gw1     = (const float*)d_in[7];  // scalar
    const float* gb      = (const float*)d_in[8];  // scalar
    float* out = (float*)d_out;

    cudaFuncSetAttribute(mega_kernel,
                         cudaFuncAttributeMaxDynamicSharedMemorySize,
                         SCORES_SMEM * (int)sizeof(float));

    prep_kw<<<dim3(HH/256, 8), 256>>>(Wq, keys, rel);
    mega_kernel<<<NGRID, 256, SCORES_SMEM * sizeof(float)>>>(
        hidden, paw, primary, vals, gw1, gb, out);
}